// round 9
// baseline (speedup 1.0000x reference)
#include <cuda_runtime.h>
#include <cuda_fp16.h>
#include <cstdint>

// ============================================================================
// Problem constants
// ============================================================================
#define NUM_EXPERTS 8
#define HIDDEN      2048
#define INTER       5504
#define TOKENS      16384
#define T_PER_E     2048

#define BK          64               // f16 elems per k-chunk = 128 bytes/row
#define TILE128_B   16384            // 128 rows * 128 bytes
#define TILE256_B   32768            // 256 rows * 128 bytes

// GEMM1: M tiles 16, N tiles 43 (5504/128), K chunks 32 (2048/64)
#define G1_NT       43
#define G1_KIT      32
#define G1_STAGE_B  (3 * TILE128_B)       // A + G + U = 48 KB per chunk
#define G1_SMEM     (4 * G1_STAGE_B)      // 196608 (2 big groups of 2 chunks)

// GEMM2: M tiles 16, N tiles 8 (2048/256), K chunks 86 (5504/64)
#define G2_NT       8
#define G2_KIT      86
#define G2_STAGE_B  (TILE128_B + TILE256_B)    // A + B = 48 KB per chunk
#define G2_SMEM     (4 * G2_STAGE_B)           // 196608

#define SWZ(o) ((o) ^ ((((uint32_t)(o)) >> 3) & 0x70))

// Epilogue staging pitches (bank-conflict-aware)
#define EP1_PITCH_H 136              // halfs per row (272 B)
#define EP2_PITCH_F 264              // floats per row (1056 B)

// ============================================================================
// Scratch (device globals — allocation is forbidden)
// ============================================================================
__device__ __align__(256) __half g_xh[(size_t)TOKENS * HIDDEN];              //  67 MB
__device__ __align__(256) __half g_gt[(size_t)NUM_EXPERTS * INTER * HIDDEN]; // 180 MB [e][i][h]
__device__ __align__(256) __half g_ut[(size_t)NUM_EXPERTS * INTER * HIDDEN]; // 180 MB [e][i][h]
__device__ __align__(256) __half g_dt[(size_t)NUM_EXPERTS * HIDDEN * INTER]; // 180 MB [e][h][i]
__device__ __align__(256) __half g_h [(size_t)TOKENS * INTER];               // 180 MB [t][i]

// ============================================================================
// Helpers (base-compute_103 features only: cp.async / ldmatrix / mma.sync)
// ============================================================================
__device__ __forceinline__ uint32_t smem_u32(const void* p) {
    uint32_t a;
    asm("{ .reg .u64 t; cvta.to.shared.u64 t, %1; cvt.u32.u64 %0, t; }"
        : "=r"(a) : "l"(p));
    return a;
}

__device__ __forceinline__ void cp16(uint32_t dst, const void* src) {
    asm volatile("cp.async.cg.shared.global [%0], [%1], 16;"
                 :: "r"(dst), "l"(src) : "memory");
}
#define CP_COMMIT() asm volatile("cp.async.commit_group;" ::: "memory")
#define CP_WAIT0()  asm volatile("cp.async.wait_group 0;" ::: "memory")

__device__ __forceinline__ void ldsm4(uint32_t& r0, uint32_t& r1,
                                      uint32_t& r2, uint32_t& r3, uint32_t a) {
    asm volatile("ldmatrix.sync.aligned.m8n8.x4.shared.b16 {%0,%1,%2,%3}, [%4];"
                 : "=r"(r0), "=r"(r1), "=r"(r2), "=r"(r3) : "r"(a));
}

__device__ __forceinline__ void mma16816(float* c, const uint32_t* a, const uint32_t* b) {
    asm volatile(
        "mma.sync.aligned.m16n8k16.row.col.f32.f16.f16.f32 "
        "{%0,%1,%2,%3}, {%4,%5,%6,%7}, {%8,%9}, {%0,%1,%2,%3};"
        : "+f"(c[0]), "+f"(c[1]), "+f"(c[2]), "+f"(c[3])
        : "r"(a[0]), "r"(a[1]), "r"(a[2]), "r"(a[3]), "r"(b[0]), "r"(b[1]));
}

__device__ __forceinline__ float silu_f(float x) {
    return x / (1.0f + __expf(-x));
}

// Load a [ROWS x 64 f16] K-major tile into SW128-swizzled smem via cp.async.
template <int ROWS>
__device__ __forceinline__ void cp_tile(uint32_t stile, const __half* __restrict__ g, int ld) {
    const int t = threadIdx.x;
#pragma unroll
    for (int i = 0; i < ROWS / 32; i++) {
        int id = t + i * 256;
        int row = id >> 3, c8 = id & 7;
        uint32_t dst = stile + SWZ((uint32_t)(row * 128 + c8 * 16));
        cp16(dst, g + (size_t)row * ld + c8 * 8);
    }
}

// A-operand fragment (m16k16) via ldmatrix.x4 from a swizzled K-major tile.
__device__ __forceinline__ void load_a_frag(uint32_t* a, uint32_t stile,
                                            int mrow0, int colb, int lane) {
    int idx = lane >> 3;
    int row = mrow0 + (idx & 1) * 8 + (lane & 7);
    int cb  = colb + (idx >> 1) * 16;
    ldsm4(a[0], a[1], a[2], a[3], stile + SWZ((uint32_t)(row * 128 + cb)));
}

// B-operand fragments (n16k16 -> two n8k16 frags) from [N][K] K-major tile.
__device__ __forceinline__ void load_b_frag(uint32_t* b0, uint32_t* b1, uint32_t stile,
                                            int nrow0, int colb, int lane) {
    int idx = lane >> 3;
    int row = nrow0 + (idx >> 1) * 8 + (lane & 7);
    int cb  = colb + (idx & 1) * 16;
    ldsm4(b0[0], b0[1], b1[0], b1[1], stile + SWZ((uint32_t)(row * 128 + cb)));
}

// ============================================================================
// Pre-pass kernels
// ============================================================================
// x: fp32 -> fp16 streaming, 16 elems/thread (4x float4 in flight).
__global__ void __launch_bounds__(256) cvt_x_kernel(const float* __restrict__ in) {
    size_t base = ((size_t)blockIdx.x * 256 + threadIdx.x) * 4;
    float4 v[4];
#pragma unroll
    for (int j = 0; j < 4; j++)
        v[j] = reinterpret_cast<const float4*>(in)[base + j];
#pragma unroll
    for (int j = 0; j < 4; j++) {
        __half2 a = __floats2half2_rn(v[j].x, v[j].y);
        __half2 b = __floats2half2_rn(v[j].z, v[j].w);
        uint2 o;
        o.x = *reinterpret_cast<uint32_t*>(&a);
        o.y = *reinterpret_cast<uint32_t*>(&b);
        reinterpret_cast<uint2*>(g_xh)[base + j] = o;
    }
}

// Transpose+convert: in [E][R][C] fp32 -> out [E][C][R] fp16.
// 64x64 tile per 256-thread block; float4 loads, uint2 (8B) fp16 stores.
__global__ void __launch_bounds__(256) transpose_kernel(const float* __restrict__ in,
                                                        int which, int R, int C) {
    __shared__ float s[64][65];
    __half* outp = (which == 0) ? g_gt : (which == 1) ? g_ut : g_dt;
    size_t base = (size_t)blockIdx.z * (size_t)R * C;
    const float* src = in + base;
    __half* dst = outp + base;
    const int c0 = blockIdx.x * 64, r0 = blockIdx.y * 64;
    const int t = threadIdx.x;
    const int tr = t >> 4;           // 0..15
    const int tc4 = t & 15;          // float4 index 0..15

    float4 v[4];
#pragma unroll
    for (int i = 0; i < 4; i++) {
        int row = tr + i * 16;
        v[i] = *reinterpret_cast<const float4*>(src + (size_t)(r0 + row) * C + c0 + tc4 * 4);
    }
#pragma unroll
    for (int i = 0; i < 4; i++) {
        int row = tr + i * 16;
        s[row][tc4 * 4 + 0] = v[i].x;
        s[row][tc4 * 4 + 1] = v[i].y;
        s[row][tc4 * 4 + 2] = v[i].z;
        s[row][tc4 * 4 + 3] = v[i].w;
    }
    __syncthreads();
#pragma unroll
    for (int p = 0; p < 4; p++) {
        int c = tr + p * 16;         // output row (original column)
        int r4 = tc4 * 4;            // 4 consecutive original rows
        __half2 h0 = __floats2half2_rn(s[r4 + 0][c], s[r4 + 1][c]);
        __half2 h1 = __floats2half2_rn(s[r4 + 2][c], s[r4 + 3][c]);
        uint2 o;
        o.x = *reinterpret_cast<uint32_t*>(&h0);
        o.y = *reinterpret_cast<uint32_t*>(&h1);
        *reinterpret_cast<uint2*>(dst + (size_t)(c0 + c) * R + r0 + r4) = o;
    }
}

// ============================================================================
// GEMM1: g = x@gate, u = x@up, h = silu(g)*u  -> g_h (fp16)
// CTA 128x128, 8 warps (4m x 2n), warp 32x64, dual accumulators.
// Double-chunk pipeline: 2 chunks (128 K) per wait+sync, 2 big groups in ring.
// ============================================================================
__global__ void __launch_bounds__(256, 1) gemm1_kernel() {
    extern __shared__ char smem[];
    uint32_t sb = smem_u32(smem);

    const int tid = threadIdx.x, wid = tid >> 5, lane = tid & 31;
    const int bid = blockIdx.x;
    const int mt = bid % 16;
    const int nt = (bid / 16) % G1_NT;
    const int e  = bid / (16 * G1_NT);
    const size_t m0 = (size_t)e * T_PER_E + (size_t)mt * 128;
    const int n0 = nt * 128;

    const __half* A = g_xh + m0 * HIDDEN;
    const __half* G = g_gt + ((size_t)e * INTER + n0) * HIDDEN;
    const __half* U = g_ut + ((size_t)e * INTER + n0) * HIDDEN;

    const int warp_m = (wid >> 1) * 32;
    const int warp_n = (wid & 1) * 64;

    // Prologue: big group 0 = chunks 0,1 -> half 0 (small stages 0,1)
#pragma unroll
    for (int c = 0; c < 2; c++) {
        uint32_t base = sb + c * G1_STAGE_B;
        cp_tile<128>(base,                 A + c * BK, HIDDEN);
        cp_tile<128>(base + TILE128_B,     G + c * BK, HIDDEN);
        cp_tile<128>(base + 2 * TILE128_B, U + c * BK, HIDDEN);
    }
    CP_COMMIT();

    float ag[2][8][4], au[2][8][4];
#pragma unroll
    for (int i = 0; i < 2; i++)
#pragma unroll
        for (int j = 0; j < 8; j++)
#pragma unroll
            for (int k = 0; k < 4; k++) { ag[i][j][k] = 0.f; au[i][j][k] = 0.f; }

#pragma unroll 1
    for (int db = 0; db < G1_KIT / 2; db++) {
        CP_WAIT0();            // big group db resident (sole outstanding group)
        __syncthreads();       // all readers of the other half are done too
        if (db + 1 < G1_KIT / 2) {
            uint32_t hb = sb + ((db + 1) & 1) * (2 * G1_STAGE_B);
            size_t k0 = (size_t)(2 * db + 2) * BK;
#pragma unroll
            for (int c = 0; c < 2; c++) {
                uint32_t base = hb + c * G1_STAGE_B;
                cp_tile<128>(base,                 A + k0 + c * BK, HIDDEN);
                cp_tile<128>(base + TILE128_B,     G + k0 + c * BK, HIDDEN);
                cp_tile<128>(base + 2 * TILE128_B, U + k0 + c * BK, HIDDEN);
            }
            CP_COMMIT();
        }
        uint32_t hb = sb + (db & 1) * (2 * G1_STAGE_B);
#pragma unroll
        for (int c = 0; c < 2; c++) {
            uint32_t st = hb + c * G1_STAGE_B;
            uint32_t sA = st, sG = st + TILE128_B, sU = st + 2 * TILE128_B;
#pragma unroll
            for (int ks = 0; ks < 4; ks++) {
                const int colb = ks * 32;
                uint32_t a[2][4], bg[8][2], bu[8][2];
#pragma unroll
                for (int m = 0; m < 2; m++)
                    load_a_frag(a[m], sA, warp_m + m * 16, colb, lane);
#pragma unroll
                for (int np = 0; np < 4; np++) {
                    load_b_frag(bg[2*np], bg[2*np+1], sG, warp_n + np * 16, colb, lane);
                    load_b_frag(bu[2*np], bu[2*np+1], sU, warp_n + np * 16, colb, lane);
                }
#pragma unroll
                for (int m = 0; m < 2; m++)
#pragma unroll
                    for (int n = 0; n < 8; n++) {
                        mma16816(ag[m][n], a[m], bg[n]);
                        mma16816(au[m][n], a[m], bu[n]);
                    }
            }
        }
    }

    // ---- Fused SwiGLU epilogue, staged through smem for coalesced stores ----
    CP_WAIT0();
    __syncthreads();
    __half* hs = reinterpret_cast<__half*>(smem);   // 128 x EP1_PITCH_H halfs
#pragma unroll
    for (int m = 0; m < 2; m++)
#pragma unroll
        for (int n = 0; n < 8; n++) {
            int row = warp_m + m * 16 + (lane >> 2);
            int col = warp_n + n * 8 + (lane & 3) * 2;
            __half2 h0 = __floats2half2_rn(silu_f(ag[m][n][0]) * au[m][n][0],
                                           silu_f(ag[m][n][1]) * au[m][n][1]);
            __half2 h1 = __floats2half2_rn(silu_f(ag[m][n][2]) * au[m][n][2],
                                           silu_f(ag[m][n][3]) * au[m][n][3]);
            *reinterpret_cast<__half2*>(hs + (size_t)row * EP1_PITCH_H + col) = h0;
            *reinterpret_cast<__half2*>(hs + (size_t)(row + 8) * EP1_PITCH_H + col) = h1;
        }
    __syncthreads();
    {
        // 256 threads: row = tid>>1, 64-half (128 B) segment = tid&1
        int row = tid >> 1, seg = tid & 1;
        const uint4* src = reinterpret_cast<const uint4*>(hs + (size_t)row * EP1_PITCH_H + seg * 64);
        uint4* dst = reinterpret_cast<uint4*>(g_h + (m0 + row) * (size_t)INTER + n0 + seg * 64);
#pragma unroll
        for (int i = 0; i < 8; i++) dst[i] = src[i];
    }
}

// ============================================================================
// GEMM2: out = h @ down  (fp32 out)
// CTA 128x256, 8 warps (2m x 4n), warp 64x64. Double-chunk pipeline.
// ============================================================================
__global__ void __launch_bounds__(256, 1) gemm2_kernel(float* __restrict__ out) {
    extern __shared__ char smem[];
    uint32_t sb = smem_u32(smem);

    const int tid = threadIdx.x, wid = tid >> 5, lane = tid & 31;
    const int bid = blockIdx.x;
    const int mt = bid % 16;
    const int nt = (bid / 16) % G2_NT;
    const int e  = bid / (16 * G2_NT);
    const size_t m0 = (size_t)e * T_PER_E + (size_t)mt * 128;
    const int n0 = nt * 256;

    const __half* A = g_h + m0 * INTER;
    const __half* B = g_dt + ((size_t)e * HIDDEN + n0) * INTER;

    const int warp_m = (wid & 1) * 64;
    const int warp_n = (wid >> 1) * 64;

    // Prologue: big group 0 = chunks 0,1 -> half 0
#pragma unroll
    for (int c = 0; c < 2; c++) {
        uint32_t base = sb + c * G2_STAGE_B;
        cp_tile<128>(base,             A + c * BK, INTER);
        cp_tile<256>(base + TILE128_B, B + c * BK, INTER);
    }
    CP_COMMIT();

    float acc[4][8][4];
#pragma unroll
    for (int i = 0; i < 4; i++)
#pragma unroll
        for (int j = 0; j < 8; j++)
#pragma unroll
            for (int k = 0; k < 4; k++) acc[i][j][k] = 0.f;

#pragma unroll 1
    for (int db = 0; db < G2_KIT / 2; db++) {
        CP_WAIT0();
        __syncthreads();
        if (db + 1 < G2_KIT / 2) {
            uint32_t hb = sb + ((db + 1) & 1) * (2 * G2_STAGE_B);
            size_t k0 = (size_t)(2 * db + 2) * BK;
#pragma unroll
            for (int c = 0; c < 2; c++) {
                uint32_t base = hb + c * G2_STAGE_B;
                cp_tile<128>(base,             A + k0 + c * BK, INTER);
                cp_tile<256>(base + TILE128_B, B + k0 + c * BK, INTER);
            }
            CP_COMMIT();
        }
        uint32_t hb = sb + (db & 1) * (2 * G2_STAGE_B);
#pragma unroll
        for (int c = 0; c < 2; c++) {
            uint32_t st = hb + c * G2_STAGE_B;
            uint32_t sA = st, sB = st + TILE128_B;
#pragma unroll
            for (int ks = 0; ks < 4; ks++) {
                const int colb = ks * 32;
                uint32_t a[4][4], b[8][2];
#pragma unroll
                for (int m = 0; m < 4; m++)
                    load_a_frag(a[m], sA, warp_m + m * 16, colb, lane);
#pragma unroll
                for (int np = 0; np < 4; np++)
                    load_b_frag(b[2*np], b[2*np+1], sB, warp_n + np * 16, colb, lane);
#pragma unroll
                for (int m = 0; m < 4; m++)
#pragma unroll
                    for (int n = 0; n < 8; n++)
                        mma16816(acc[m][n], a[m], b[n]);
            }
        }
    }

    // ---- fp32 epilogue staged through smem for coalesced 128B stores ----
    CP_WAIT0();
    __syncthreads();
    float* fs = reinterpret_cast<float*>(smem);   // 128 x EP2_PITCH_F floats
#pragma unroll
    for (int m = 0; m < 4; m++)
#pragma unroll
        for (int n = 0; n < 8; n++) {
            int row = warp_m + m * 16 + (lane >> 2);
            int col = warp_n + n * 8 + (lane & 3) * 2;
            float2 v0 = make_float2(acc[m][n][0], acc[m][n][1]);
            float2 v1 = make_float2(acc[m][n][2], acc[m][n][3]);
            *reinterpret_cast<float2*>(fs + (size_t)row * EP2_PITCH_F + col) = v0;
            *reinterpret_cast<float2*>(fs + (size_t)(row + 8) * EP2_PITCH_F + col) = v1;
        }
    __syncthreads();
    {
        int row = tid >> 1, seg = tid & 1;
        const uint4* src = reinterpret_cast<const uint4*>(fs + (size_t)row * EP2_PITCH_F + seg * 128);
        uint4* dst = reinterpret_cast<uint4*>(out + (m0 + row) * (size_t)HIDDEN + n0 + seg * 128);
#pragma unroll
        for (int i = 0; i < 32; i++) dst[i] = src[i];
    }
}

// ============================================================================
// Launch: T(dw) forked onto a second stream so it overlaps gemm1.
// ============================================================================
extern "C" void kernel_launch(void* const* d_in, const int* in_sizes, int n_in,
                              void* d_out, int out_size) {
    const float* x  = (const float*)d_in[0];
    const float* gw = (const float*)d_in[1];
    const float* uw = (const float*)d_in[2];
    const float* dw = (const float*)d_in[3];
    float* out = (float*)d_out;

    cudaFuncSetAttribute(gemm1_kernel, cudaFuncAttributeMaxDynamicSharedMemorySize, G1_SMEM);
    cudaFuncSetAttribute(gemm2_kernel, cudaFuncAttributeMaxDynamicSharedMemorySize, G2_SMEM);

    cudaStream_t s2;
    cudaEvent_t e_fork, e_join;
    cudaStreamCreateWithFlags(&s2, cudaStreamNonBlocking);
    cudaEventCreateWithFlags(&e_fork, cudaEventDisableTiming);
    cudaEventCreateWithFlags(&e_join, cudaEventDisableTiming);

    // Fork: T(dw) depends only on input dw; run it concurrently with the
    // gemm1-critical path (cvt_x, T(gw), T(uw), gemm1).
    cudaEventRecord(e_fork, 0);
    cudaStreamWaitEvent(s2, e_fork, 0);
    transpose_kernel<<<dim3(HIDDEN / 64, INTER / 64, NUM_EXPERTS), 256, 0, s2>>>(dw, 2, INTER, HIDDEN);
    cudaEventRecord(e_join, s2);

    // Main chain on the default (capture) stream.
    cvt_x_kernel<<<(TOKENS * (size_t)HIDDEN / 16) / 256, 256>>>(x);
    transpose_kernel<<<dim3(INTER / 64, HIDDEN / 64, NUM_EXPERTS), 256>>>(gw, 0, HIDDEN, INTER);
    transpose_kernel<<<dim3(INTER / 64, HIDDEN / 64, NUM_EXPERTS), 256>>>(uw, 1, HIDDEN, INTER);
    gemm1_kernel<<<NUM_EXPERTS * G1_NT * 16, 256, G1_SMEM>>>();

    // Join: gemm2 needs g_dt (from the forked transpose) and g_h (from gemm1).
    cudaStreamWaitEvent(0, e_join, 0);
    gemm2_kernel<<<NUM_EXPERTS * G2_NT * 16, 256, G2_SMEM>>>(out);
}

// round 10
// speedup vs baseline: 1.5388x; 1.5388x over previous
#include <cuda_runtime.h>
#include <cuda_fp16.h>
#include <cstdint>

// ============================================================================
// Problem constants
// ============================================================================
#define NUM_EXPERTS 8
#define HIDDEN      2048
#define INTER       5504
#define TOKENS      16384
#define T_PER_E     2048

#define BK          64               // f16 elems per k-chunk = 128 bytes/row
#define TILE128_B   16384            // 128 rows * 128 bytes
#define TILE256_B   32768            // 256 rows * 128 bytes

// GEMM1: M tiles 16, N tiles 43 (5504/128), K chunks 32 (2048/64)
#define G1_NT       43
#define G1_KIT      32
#define G1_STAGE_B  (3 * TILE128_B)       // A + G + U = 48 KB per chunk
#define G1_SMEM     (4 * G1_STAGE_B)      // 196608 (2 big groups of 2 chunks)

// GEMM2: M tiles 16, N tiles 8 (2048/256), K chunks 86 (5504/64)
#define G2_NT       8
#define G2_KIT      86
#define G2_STAGE_B  (TILE128_B + TILE256_B)    // A + B = 48 KB per chunk
#define G2_SMEM     (4 * G2_STAGE_B)           // 196608

#define SWZ(o) ((o) ^ ((((uint32_t)(o)) >> 3) & 0x70))

// Epilogue staging pitches (bank-conflict-aware)
#define EP1_PITCH_H 136              // halfs per row (272 B)
#define EP2_PITCH_F 264              // floats per row (1056 B)

// Prepass fused-grid layout
#define CVT_BLKS    8192                       // TOKENS*HIDDEN/16/256
#define TW_BLKS     22016                      // 86*32*8 (= 32*86*8)
#define PRE_BLKS    (CVT_BLKS + 3 * TW_BLKS)   // 74240

// ============================================================================
// Scratch (device globals — allocation is forbidden)
// ============================================================================
__device__ __align__(256) __half g_xh[(size_t)TOKENS * HIDDEN];              //  67 MB
__device__ __align__(256) __half g_gt[(size_t)NUM_EXPERTS * INTER * HIDDEN]; // 180 MB [e][i][h]
__device__ __align__(256) __half g_ut[(size_t)NUM_EXPERTS * INTER * HIDDEN]; // 180 MB [e][i][h]
__device__ __align__(256) __half g_dt[(size_t)NUM_EXPERTS * HIDDEN * INTER]; // 180 MB [e][h][i]
__device__ __align__(256) __half g_h [(size_t)TOKENS * INTER];               // 180 MB [t][i]

// ============================================================================
// Helpers (base-compute_103 features only: cp.async / ldmatrix / mma.sync)
// ============================================================================
__device__ __forceinline__ uint32_t smem_u32(const void* p) {
    uint32_t a;
    asm("{ .reg .u64 t; cvta.to.shared.u64 t, %1; cvt.u32.u64 %0, t; }"
        : "=r"(a) : "l"(p));
    return a;
}

__device__ __forceinline__ void cp16(uint32_t dst, const void* src) {
    asm volatile("cp.async.cg.shared.global [%0], [%1], 16;"
                 :: "r"(dst), "l"(src) : "memory");
}
#define CP_COMMIT() asm volatile("cp.async.commit_group;" ::: "memory")
#define CP_WAIT0()  asm volatile("cp.async.wait_group 0;" ::: "memory")

__device__ __forceinline__ void ldsm4(uint32_t& r0, uint32_t& r1,
                                      uint32_t& r2, uint32_t& r3, uint32_t a) {
    asm volatile("ldmatrix.sync.aligned.m8n8.x4.shared.b16 {%0,%1,%2,%3}, [%4];"
                 : "=r"(r0), "=r"(r1), "=r"(r2), "=r"(r3) : "r"(a));
}

__device__ __forceinline__ void mma16816(float* c, const uint32_t* a, const uint32_t* b) {
    asm volatile(
        "mma.sync.aligned.m16n8k16.row.col.f32.f16.f16.f32 "
        "{%0,%1,%2,%3}, {%4,%5,%6,%7}, {%8,%9}, {%0,%1,%2,%3};"
        : "+f"(c[0]), "+f"(c[1]), "+f"(c[2]), "+f"(c[3])
        : "r"(a[0]), "r"(a[1]), "r"(a[2]), "r"(a[3]), "r"(b[0]), "r"(b[1]));
}

__device__ __forceinline__ float silu_f(float x) {
    return x / (1.0f + __expf(-x));
}

// Load a [ROWS x 64 f16] K-major tile into SW128-swizzled smem via cp.async.
template <int ROWS>
__device__ __forceinline__ void cp_tile(uint32_t stile, const __half* __restrict__ g, int ld) {
    const int t = threadIdx.x;
#pragma unroll
    for (int i = 0; i < ROWS / 32; i++) {
        int id = t + i * 256;
        int row = id >> 3, c8 = id & 7;
        uint32_t dst = stile + SWZ((uint32_t)(row * 128 + c8 * 16));
        cp16(dst, g + (size_t)row * ld + c8 * 8);
    }
}

// A-operand fragment (m16k16) via ldmatrix.x4 from a swizzled K-major tile.
__device__ __forceinline__ void load_a_frag(uint32_t* a, uint32_t stile,
                                            int mrow0, int colb, int lane) {
    int idx = lane >> 3;
    int row = mrow0 + (idx & 1) * 8 + (lane & 7);
    int cb  = colb + (idx >> 1) * 16;
    ldsm4(a[0], a[1], a[2], a[3], stile + SWZ((uint32_t)(row * 128 + cb)));
}

// B-operand fragments (n16k16 -> two n8k16 frags) from [N][K] K-major tile.
__device__ __forceinline__ void load_b_frag(uint32_t* b0, uint32_t* b1, uint32_t stile,
                                            int nrow0, int colb, int lane) {
    int idx = lane >> 3;
    int row = nrow0 + (idx >> 1) * 8 + (lane & 7);
    int cb  = colb + (idx & 1) * 16;
    ldsm4(b0[0], b0[1], b1[0], b1[1], stile + SWZ((uint32_t)(row * 128 + cb)));
}

// ============================================================================
// Fused pre-pass: one launch covers
//   [0, CVT_BLKS)                        : x fp32 -> fp16 streaming
//   [CVT_BLKS + w*TW_BLKS, ...)  w=0,1,2 : transpose+convert gw / uw / dw
// ============================================================================
__device__ __forceinline__ void transpose_body(const float* __restrict__ src,
                                               __half* __restrict__ dst,
                                               int R, int C, int bx, int by,
                                               float (*s)[65]) {
    const int c0 = bx * 64, r0 = by * 64;
    const int t = threadIdx.x;
    const int tr = t >> 4;           // 0..15
    const int tc4 = t & 15;          // float4 index 0..15

    float4 v[4];
#pragma unroll
    for (int i = 0; i < 4; i++) {
        int row = tr + i * 16;
        v[i] = *reinterpret_cast<const float4*>(src + (size_t)(r0 + row) * C + c0 + tc4 * 4);
    }
#pragma unroll
    for (int i = 0; i < 4; i++) {
        int row = tr + i * 16;
        s[row][tc4 * 4 + 0] = v[i].x;
        s[row][tc4 * 4 + 1] = v[i].y;
        s[row][tc4 * 4 + 2] = v[i].z;
        s[row][tc4 * 4 + 3] = v[i].w;
    }
    __syncthreads();
#pragma unroll
    for (int p = 0; p < 4; p++) {
        int c = tr + p * 16;         // output row (original column)
        int r4 = tc4 * 4;            // 4 consecutive original rows
        __half2 h0 = __floats2half2_rn(s[r4 + 0][c], s[r4 + 1][c]);
        __half2 h1 = __floats2half2_rn(s[r4 + 2][c], s[r4 + 3][c]);
        uint2 o;
        o.x = *reinterpret_cast<uint32_t*>(&h0);
        o.y = *reinterpret_cast<uint32_t*>(&h1);
        *reinterpret_cast<uint2*>(dst + (size_t)(c0 + c) * R + r0 + r4) = o;
    }
}

__global__ void __launch_bounds__(256) prepass_kernel(const float* __restrict__ x,
                                                      const float* __restrict__ gw,
                                                      const float* __restrict__ uw,
                                                      const float* __restrict__ dw) {
    __shared__ float s[64][65];
    int b = blockIdx.x;

    if (b < CVT_BLKS) {
        // x: fp32 -> fp16 streaming, 16 elems/thread (4x float4 in flight).
        size_t base = ((size_t)b * 256 + threadIdx.x) * 4;
        float4 v[4];
#pragma unroll
        for (int j = 0; j < 4; j++)
            v[j] = reinterpret_cast<const float4*>(x)[base + j];
#pragma unroll
        for (int j = 0; j < 4; j++) {
            __half2 a = __floats2half2_rn(v[j].x, v[j].y);
            __half2 bb = __floats2half2_rn(v[j].z, v[j].w);
            uint2 o;
            o.x = *reinterpret_cast<uint32_t*>(&a);
            o.y = *reinterpret_cast<uint32_t*>(&bb);
            reinterpret_cast<uint2*>(g_xh)[base + j] = o;
        }
        return;
    }
    b -= CVT_BLKS;
    const int which = b / TW_BLKS;
    const int r = b % TW_BLKS;

    if (which < 2) {
        // gate/up: in [E][HIDDEN][INTER] -> out [E][INTER][HIDDEN]
        const int bx = r % (INTER / 64);
        const int by = (r / (INTER / 64)) % (HIDDEN / 64);
        const int bz = r / ((INTER / 64) * (HIDDEN / 64));
        const float* src = (which == 0 ? gw : uw) + (size_t)bz * HIDDEN * INTER;
        __half* dst = (which == 0 ? g_gt : g_ut) + (size_t)bz * HIDDEN * INTER;
        transpose_body(src, dst, HIDDEN, INTER, bx, by, s);
    } else {
        // down: in [E][INTER][HIDDEN] -> out [E][HIDDEN][INTER]
        const int bx = r % (HIDDEN / 64);
        const int by = (r / (HIDDEN / 64)) % (INTER / 64);
        const int bz = r / ((HIDDEN / 64) * (INTER / 64));
        const float* src = dw + (size_t)bz * INTER * HIDDEN;
        __half* dst = g_dt + (size_t)bz * INTER * HIDDEN;
        transpose_body(src, dst, INTER, HIDDEN, bx, by, s);
    }
}

// ============================================================================
// GEMM1: g = x@gate, u = x@up, h = silu(g)*u  -> g_h (fp16)
// CTA 128x128, 8 warps (4m x 2n), warp 32x64, dual accumulators.
// Double-chunk pipeline: 2 chunks (128 K) per wait+sync, 2 big groups in ring.
// ============================================================================
__global__ void __launch_bounds__(256, 1) gemm1_kernel() {
    extern __shared__ char smem[];
    uint32_t sb = smem_u32(smem);

    const int tid = threadIdx.x, wid = tid >> 5, lane = tid & 31;
    const int bid = blockIdx.x;
    const int mt = bid % 16;
    const int nt = (bid / 16) % G1_NT;
    const int e  = bid / (16 * G1_NT);
    const size_t m0 = (size_t)e * T_PER_E + (size_t)mt * 128;
    const int n0 = nt * 128;

    const __half* A = g_xh + m0 * HIDDEN;
    const __half* G = g_gt + ((size_t)e * INTER + n0) * HIDDEN;
    const __half* U = g_ut + ((size_t)e * INTER + n0) * HIDDEN;

    const int warp_m = (wid >> 1) * 32;
    const int warp_n = (wid & 1) * 64;

    // Prologue: big group 0 = chunks 0,1 -> half 0 (small stages 0,1)
#pragma unroll
    for (int c = 0; c < 2; c++) {
        uint32_t base = sb + c * G1_STAGE_B;
        cp_tile<128>(base,                 A + c * BK, HIDDEN);
        cp_tile<128>(base + TILE128_B,     G + c * BK, HIDDEN);
        cp_tile<128>(base + 2 * TILE128_B, U + c * BK, HIDDEN);
    }
    CP_COMMIT();

    float ag[2][8][4], au[2][8][4];
#pragma unroll
    for (int i = 0; i < 2; i++)
#pragma unroll
        for (int j = 0; j < 8; j++)
#pragma unroll
            for (int k = 0; k < 4; k++) { ag[i][j][k] = 0.f; au[i][j][k] = 0.f; }

#pragma unroll 1
    for (int db = 0; db < G1_KIT / 2; db++) {
        CP_WAIT0();            // big group db resident (sole outstanding group)
        __syncthreads();       // all readers of the other half are done too
        if (db + 1 < G1_KIT / 2) {
            uint32_t hb = sb + ((db + 1) & 1) * (2 * G1_STAGE_B);
            size_t k0 = (size_t)(2 * db + 2) * BK;
#pragma unroll
            for (int c = 0; c < 2; c++) {
                uint32_t base = hb + c * G1_STAGE_B;
                cp_tile<128>(base,                 A + k0 + c * BK, HIDDEN);
                cp_tile<128>(base + TILE128_B,     G + k0 + c * BK, HIDDEN);
                cp_tile<128>(base + 2 * TILE128_B, U + k0 + c * BK, HIDDEN);
            }
            CP_COMMIT();
        }
        uint32_t hb = sb + (db & 1) * (2 * G1_STAGE_B);
#pragma unroll
        for (int c = 0; c < 2; c++) {
            uint32_t st = hb + c * G1_STAGE_B;
            uint32_t sA = st, sG = st + TILE128_B, sU = st + 2 * TILE128_B;
#pragma unroll
            for (int ks = 0; ks < 4; ks++) {
                const int colb = ks * 32;
                uint32_t a[2][4], bg[8][2], bu[8][2];
#pragma unroll
                for (int m = 0; m < 2; m++)
                    load_a_frag(a[m], sA, warp_m + m * 16, colb, lane);
#pragma unroll
                for (int np = 0; np < 4; np++) {
                    load_b_frag(bg[2*np], bg[2*np+1], sG, warp_n + np * 16, colb, lane);
                    load_b_frag(bu[2*np], bu[2*np+1], sU, warp_n + np * 16, colb, lane);
                }
#pragma unroll
                for (int m = 0; m < 2; m++)
#pragma unroll
                    for (int n = 0; n < 8; n++) {
                        mma16816(ag[m][n], a[m], bg[n]);
                        mma16816(au[m][n], a[m], bu[n]);
                    }
            }
        }
    }

    // ---- Fused SwiGLU epilogue, staged through smem for coalesced stores ----
    CP_WAIT0();
    __syncthreads();
    __half* hs = reinterpret_cast<__half*>(smem);   // 128 x EP1_PITCH_H halfs
#pragma unroll
    for (int m = 0; m < 2; m++)
#pragma unroll
        for (int n = 0; n < 8; n++) {
            int row = warp_m + m * 16 + (lane >> 2);
            int col = warp_n + n * 8 + (lane & 3) * 2;
            __half2 h0 = __floats2half2_rn(silu_f(ag[m][n][0]) * au[m][n][0],
                                           silu_f(ag[m][n][1]) * au[m][n][1]);
            __half2 h1 = __floats2half2_rn(silu_f(ag[m][n][2]) * au[m][n][2],
                                           silu_f(ag[m][n][3]) * au[m][n][3]);
            *reinterpret_cast<__half2*>(hs + (size_t)row * EP1_PITCH_H + col) = h0;
            *reinterpret_cast<__half2*>(hs + (size_t)(row + 8) * EP1_PITCH_H + col) = h1;
        }
    __syncthreads();
    {
        // 256 threads: row = tid>>1, 64-half (128 B) segment = tid&1
        int row = tid >> 1, seg = tid & 1;
        const uint4* src = reinterpret_cast<const uint4*>(hs + (size_t)row * EP1_PITCH_H + seg * 64);
        uint4* dst = reinterpret_cast<uint4*>(g_h + (m0 + row) * (size_t)INTER + n0 + seg * 64);
#pragma unroll
        for (int i = 0; i < 8; i++) dst[i] = src[i];
    }
}

// ============================================================================
// GEMM2: out = h @ down  (fp32 out)
// CTA 128x256, 8 warps (2m x 4n), warp 64x64. Double-chunk pipeline.
// ============================================================================
__global__ void __launch_bounds__(256, 1) gemm2_kernel(float* __restrict__ out) {
    extern __shared__ char smem[];
    uint32_t sb = smem_u32(smem);

    const int tid = threadIdx.x, wid = tid >> 5, lane = tid & 31;
    const int bid = blockIdx.x;
    const int mt = bid % 16;
    const int nt = (bid / 16) % G2_NT;
    const int e  = bid / (16 * G2_NT);
    const size_t m0 = (size_t)e * T_PER_E + (size_t)mt * 128;
    const int n0 = nt * 256;

    const __half* A = g_h + m0 * INTER;
    const __half* B = g_dt + ((size_t)e * HIDDEN + n0) * INTER;

    const int warp_m = (wid & 1) * 64;
    const int warp_n = (wid >> 1) * 64;

    // Prologue: big group 0 = chunks 0,1 -> half 0
#pragma unroll
    for (int c = 0; c < 2; c++) {
        uint32_t base = sb + c * G2_STAGE_B;
        cp_tile<128>(base,             A + c * BK, INTER);
        cp_tile<256>(base + TILE128_B, B + c * BK, INTER);
    }
    CP_COMMIT();

    float acc[4][8][4];
#pragma unroll
    for (int i = 0; i < 4; i++)
#pragma unroll
        for (int j = 0; j < 8; j++)
#pragma unroll
            for (int k = 0; k < 4; k++) acc[i][j][k] = 0.f;

#pragma unroll 1
    for (int db = 0; db < G2_KIT / 2; db++) {
        CP_WAIT0();
        __syncthreads();
        if (db + 1 < G2_KIT / 2) {
            uint32_t hb = sb + ((db + 1) & 1) * (2 * G2_STAGE_B);
            size_t k0 = (size_t)(2 * db + 2) * BK;
#pragma unroll
            for (int c = 0; c < 2; c++) {
                uint32_t base = hb + c * G2_STAGE_B;
                cp_tile<128>(base,             A + k0 + c * BK, INTER);
                cp_tile<256>(base + TILE128_B, B + k0 + c * BK, INTER);
            }
            CP_COMMIT();
        }
        uint32_t hb = sb + (db & 1) * (2 * G2_STAGE_B);
#pragma unroll
        for (int c = 0; c < 2; c++) {
            uint32_t st = hb + c * G2_STAGE_B;
            uint32_t sA = st, sB = st + TILE128_B;
#pragma unroll
            for (int ks = 0; ks < 4; ks++) {
                const int colb = ks * 32;
                uint32_t a[4][4], b[8][2];
#pragma unroll
                for (int m = 0; m < 4; m++)
                    load_a_frag(a[m], sA, warp_m + m * 16, colb, lane);
#pragma unroll
                for (int np = 0; np < 4; np++)
                    load_b_frag(b[2*np], b[2*np+1], sB, warp_n + np * 16, colb, lane);
#pragma unroll
                for (int m = 0; m < 4; m++)
#pragma unroll
                    for (int n = 0; n < 8; n++)
                        mma16816(acc[m][n], a[m], b[n]);
            }
        }
    }

    // ---- fp32 epilogue staged through smem for coalesced 128B stores ----
    CP_WAIT0();
    __syncthreads();
    float* fs = reinterpret_cast<float*>(smem);   // 128 x EP2_PITCH_F floats
#pragma unroll
    for (int m = 0; m < 4; m++)
#pragma unroll
        for (int n = 0; n < 8; n++) {
            int row = warp_m + m * 16 + (lane >> 2);
            int col = warp_n + n * 8 + (lane & 3) * 2;
            float2 v0 = make_float2(acc[m][n][0], acc[m][n][1]);
            float2 v1 = make_float2(acc[m][n][2], acc[m][n][3]);
            *reinterpret_cast<float2*>(fs + (size_t)row * EP2_PITCH_F + col) = v0;
            *reinterpret_cast<float2*>(fs + (size_t)(row + 8) * EP2_PITCH_F + col) = v1;
        }
    __syncthreads();
    {
        int row = tid >> 1, seg = tid & 1;
        const uint4* src = reinterpret_cast<const uint4*>(fs + (size_t)row * EP2_PITCH_F + seg * 128);
        uint4* dst = reinterpret_cast<uint4*>(out + (m0 + row) * (size_t)HIDDEN + n0 + seg * 128);
#pragma unroll
        for (int i = 0; i < 32; i++) dst[i] = src[i];
    }
}

// ============================================================================
// Launch (single stream, linear graph)
// ============================================================================
extern "C" void kernel_launch(void* const* d_in, const int* in_sizes, int n_in,
                              void* d_out, int out_size) {
    const float* x  = (const float*)d_in[0];
    const float* gw = (const float*)d_in[1];
    const float* uw = (const float*)d_in[2];
    const float* dw = (const float*)d_in[3];
    float* out = (float*)d_out;

    cudaFuncSetAttribute(gemm1_kernel, cudaFuncAttributeMaxDynamicSharedMemorySize, G1_SMEM);
    cudaFuncSetAttribute(gemm2_kernel, cudaFuncAttributeMaxDynamicSharedMemorySize, G2_SMEM);

    // Fused pre-pass: cvt(x) + transpose(gw) + transpose(uw) + transpose(dw)
    prepass_kernel<<<PRE_BLKS, 256>>>(x, gw, uw, dw);

    // GEMMs
    gemm1_kernel<<<NUM_EXPERTS * G1_NT * 16, 256, G1_SMEM>>>();
    gemm2_kernel<<<NUM_EXPERTS * G2_NT * 16, 256, G2_SMEM>>>(out);
}

// round 11
// speedup vs baseline: 1.6263x; 1.0568x over previous
#include <cuda_runtime.h>
#include <cuda_fp16.h>
#include <cstdint>

// ============================================================================
// Problem constants
// ============================================================================
#define NUM_EXPERTS 8
#define HIDDEN      2048
#define INTER       5504
#define TOKENS      16384
#define T_PER_E     2048

#define BK          64               // f16 elems per k-chunk = 128 bytes/row
#define TILE128_B   16384            // 128 rows * 128 bytes
#define TILE256_B   32768            // 256 rows * 128 bytes

// GEMM1: M tiles 16, N tiles 43 (5504/128), K chunks 32 (2048/64)
#define G1_NT       43
#define G1_KIT      32
#define G1_STAGE_B  (3 * TILE128_B)       // A + G + U = 48 KB per chunk
#define G1_SMEM     (4 * G1_STAGE_B)      // 196608 (2 big groups of 2 chunks)

// GEMM2: M tiles 16, N tiles 8 (2048/256), K chunks 86 (5504/64)
#define G2_NT       8
#define G2_KIT      86
#define G2_STAGE_B  (TILE128_B + TILE256_B)    // A + B = 48 KB per chunk
#define G2_SMEM     (4 * G2_STAGE_B)           // 196608

#define SWZ(o) ((o) ^ ((((uint32_t)(o)) >> 3) & 0x70))

// Epilogue staging pitches (bank-conflict-aware)
#define EP1_PITCH_H 136              // halfs per row (272 B)
#define EP2_PITCH_F 264              // floats per row (1056 B)

// Prepass fused-grid layout
#define CVT_BLKS    8192                       // TOKENS*HIDDEN/16/256
#define TW_BLKS     22016                      // 86*32*8
#define PRE_BLKS    (CVT_BLKS + 3 * TW_BLKS)   // 74240

// ============================================================================
// Scratch (device globals — allocation is forbidden)
// ============================================================================
__device__ __align__(256) __half g_xh[(size_t)TOKENS * HIDDEN];              //  67 MB
__device__ __align__(256) __half g_gt[(size_t)NUM_EXPERTS * INTER * HIDDEN]; // 180 MB [e][i][h]
__device__ __align__(256) __half g_ut[(size_t)NUM_EXPERTS * INTER * HIDDEN]; // 180 MB [e][i][h]
__device__ __align__(256) __half g_dt[(size_t)NUM_EXPERTS * HIDDEN * INTER]; // 180 MB [e][h][i]
__device__ __align__(256) __half g_h [(size_t)TOKENS * INTER];               // 180 MB [t][i]

// ============================================================================
// Helpers (base-compute_103 features only: cp.async / ldmatrix / mma.sync)
// ============================================================================
__device__ __forceinline__ uint32_t smem_u32(const void* p) {
    uint32_t a;
    asm("{ .reg .u64 t; cvta.to.shared.u64 t, %1; cvt.u32.u64 %0, t; }"
        : "=r"(a) : "l"(p));
    return a;
}

__device__ __forceinline__ void cp16(uint32_t dst, const void* src) {
    asm volatile("cp.async.cg.shared.global [%0], [%1], 16;"
                 :: "r"(dst), "l"(src) : "memory");
}
#define CP_COMMIT() asm volatile("cp.async.commit_group;" ::: "memory")
#define CP_WAIT0()  asm volatile("cp.async.wait_group 0;" ::: "memory")

__device__ __forceinline__ void ldsm4(uint32_t& r0, uint32_t& r1,
                                      uint32_t& r2, uint32_t& r3, uint32_t a) {
    asm volatile("ldmatrix.sync.aligned.m8n8.x4.shared.b16 {%0,%1,%2,%3}, [%4];"
                 : "=r"(r0), "=r"(r1), "=r"(r2), "=r"(r3) : "r"(a));
}

__device__ __forceinline__ void mma16816(float* c, const uint32_t* a, const uint32_t* b) {
    asm volatile(
        "mma.sync.aligned.m16n8k16.row.col.f32.f16.f16.f32 "
        "{%0,%1,%2,%3}, {%4,%5,%6,%7}, {%8,%9}, {%0,%1,%2,%3};"
        : "+f"(c[0]), "+f"(c[1]), "+f"(c[2]), "+f"(c[3])
        : "r"(a[0]), "r"(a[1]), "r"(a[2]), "r"(a[3]), "r"(b[0]), "r"(b[1]));
}

__device__ __forceinline__ float silu_f(float x) {
    return x / (1.0f + __expf(-x));
}

// Copy-warp tile loader: 128 threads (warps 4-7, tid-128) move a
// [ROWS x 64 f16] K-major tile into SW128-swizzled smem via cp.async.
template <int ROWS>
__device__ __forceinline__ void cp_tile_w4(uint32_t stile, const __half* __restrict__ g, int ld) {
    const int t = threadIdx.x - 128;   // 0..127 (caller guarantees wid >= 4)
#pragma unroll
    for (int i = 0; i < ROWS / 16; i++) {
        int id = t + i * 128;
        int row = id >> 3, c8 = id & 7;
        uint32_t dst = stile + SWZ((uint32_t)(row * 128 + c8 * 16));
        cp16(dst, g + (size_t)row * ld + c8 * 8);
    }
}

// A-operand fragment (m16k16) via ldmatrix.x4 from a swizzled K-major tile.
__device__ __forceinline__ void load_a_frag(uint32_t* a, uint32_t stile,
                                            int mrow0, int colb, int lane) {
    int idx = lane >> 3;
    int row = mrow0 + (idx & 1) * 8 + (lane & 7);
    int cb  = colb + (idx >> 1) * 16;
    ldsm4(a[0], a[1], a[2], a[3], stile + SWZ((uint32_t)(row * 128 + cb)));
}

// B-operand fragments (n16k16 -> two n8k16 frags) from [N][K] K-major tile.
__device__ __forceinline__ void load_b_frag(uint32_t* b0, uint32_t* b1, uint32_t stile,
                                            int nrow0, int colb, int lane) {
    int idx = lane >> 3;
    int row = nrow0 + (idx >> 1) * 8 + (lane & 7);
    int cb  = colb + (idx & 1) * 16;
    ldsm4(b0[0], b0[1], b1[0], b1[1], stile + SWZ((uint32_t)(row * 128 + cb)));
}

// ============================================================================
// Fused pre-pass (unchanged from R10: at 90% DRAM roofline)
// ============================================================================
__device__ __forceinline__ void transpose_body(const float* __restrict__ src,
                                               __half* __restrict__ dst,
                                               int R, int C, int bx, int by,
                                               float (*s)[65]) {
    const int c0 = bx * 64, r0 = by * 64;
    const int t = threadIdx.x;
    const int tr = t >> 4;
    const int tc4 = t & 15;

    float4 v[4];
#pragma unroll
    for (int i = 0; i < 4; i++) {
        int row = tr + i * 16;
        v[i] = *reinterpret_cast<const float4*>(src + (size_t)(r0 + row) * C + c0 + tc4 * 4);
    }
#pragma unroll
    for (int i = 0; i < 4; i++) {
        int row = tr + i * 16;
        s[row][tc4 * 4 + 0] = v[i].x;
        s[row][tc4 * 4 + 1] = v[i].y;
        s[row][tc4 * 4 + 2] = v[i].z;
        s[row][tc4 * 4 + 3] = v[i].w;
    }
    __syncthreads();
#pragma unroll
    for (int p = 0; p < 4; p++) {
        int c = tr + p * 16;
        int r4 = tc4 * 4;
        __half2 h0 = __floats2half2_rn(s[r4 + 0][c], s[r4 + 1][c]);
        __half2 h1 = __floats2half2_rn(s[r4 + 2][c], s[r4 + 3][c]);
        uint2 o;
        o.x = *reinterpret_cast<uint32_t*>(&h0);
        o.y = *reinterpret_cast<uint32_t*>(&h1);
        *reinterpret_cast<uint2*>(dst + (size_t)(c0 + c) * R + r0 + r4) = o;
    }
}

__global__ void __launch_bounds__(256) prepass_kernel(const float* __restrict__ x,
                                                      const float* __restrict__ gw,
                                                      const float* __restrict__ uw,
                                                      const float* __restrict__ dw) {
    __shared__ float s[64][65];
    int b = blockIdx.x;

    if (b < CVT_BLKS) {
        size_t base = ((size_t)b * 256 + threadIdx.x) * 4;
        float4 v[4];
#pragma unroll
        for (int j = 0; j < 4; j++)
            v[j] = reinterpret_cast<const float4*>(x)[base + j];
#pragma unroll
        for (int j = 0; j < 4; j++) {
            __half2 a = __floats2half2_rn(v[j].x, v[j].y);
            __half2 bb = __floats2half2_rn(v[j].z, v[j].w);
            uint2 o;
            o.x = *reinterpret_cast<uint32_t*>(&a);
            o.y = *reinterpret_cast<uint32_t*>(&bb);
            reinterpret_cast<uint2*>(g_xh)[base + j] = o;
        }
        return;
    }
    b -= CVT_BLKS;
    const int which = b / TW_BLKS;
    const int r = b % TW_BLKS;

    if (which < 2) {
        const int bx = r % (INTER / 64);
        const int by = (r / (INTER / 64)) % (HIDDEN / 64);
        const int bz = r / ((INTER / 64) * (HIDDEN / 64));
        const float* src = (which == 0 ? gw : uw) + (size_t)bz * HIDDEN * INTER;
        __half* dst = (which == 0 ? g_gt : g_ut) + (size_t)bz * HIDDEN * INTER;
        transpose_body(src, dst, HIDDEN, INTER, bx, by, s);
    } else {
        const int bx = r % (HIDDEN / 64);
        const int by = (r / (HIDDEN / 64)) % (INTER / 64);
        const int bz = r / ((HIDDEN / 64) * (INTER / 64));
        const float* src = dw + (size_t)bz * INTER * HIDDEN;
        __half* dst = g_dt + (size_t)bz * INTER * HIDDEN;
        transpose_body(src, dst, INTER, HIDDEN, bx, by, s);
    }
}

// ============================================================================
// GEMM1: g = x@gate, u = x@up, h = silu(g)*u  -> g_h (fp16)
// CTA 128x128, 8 warps (4m x 2n), warp 32x64, dual accumulators.
// Double-chunk pipeline; prefetch issued ONLY by warps 4-7 (copy-role split)
// so warps 0-3 feed the HMMA pipe immediately after each barrier.
// ============================================================================
__global__ void __launch_bounds__(256, 1) gemm1_kernel() {
    extern __shared__ char smem[];
    uint32_t sb = smem_u32(smem);

    const int tid = threadIdx.x, wid = tid >> 5, lane = tid & 31;
    const int bid = blockIdx.x;
    const int mt = bid % 16;
    const int nt = (bid / 16) % G1_NT;
    const int e  = bid / (16 * G1_NT);
    const size_t m0 = (size_t)e * T_PER_E + (size_t)mt * 128;
    const int n0 = nt * 128;

    const __half* A = g_xh + m0 * HIDDEN;
    const __half* G = g_gt + ((size_t)e * INTER + n0) * HIDDEN;
    const __half* U = g_ut + ((size_t)e * INTER + n0) * HIDDEN;

    const int warp_m = (wid >> 1) * 32;
    const int warp_n = (wid & 1) * 64;
    const bool copier = (wid >= 4);

    // Prologue: big group 0 = chunks 0,1 -> half 0 (copy warps only)
    if (copier) {
#pragma unroll
        for (int c = 0; c < 2; c++) {
            uint32_t base = sb + c * G1_STAGE_B;
            cp_tile_w4<128>(base,                 A + c * BK, HIDDEN);
            cp_tile_w4<128>(base + TILE128_B,     G + c * BK, HIDDEN);
            cp_tile_w4<128>(base + 2 * TILE128_B, U + c * BK, HIDDEN);
        }
        CP_COMMIT();
    }

    float ag[2][8][4], au[2][8][4];
#pragma unroll
    for (int i = 0; i < 2; i++)
#pragma unroll
        for (int j = 0; j < 8; j++)
#pragma unroll
            for (int k = 0; k < 4; k++) { ag[i][j][k] = 0.f; au[i][j][k] = 0.f; }

#pragma unroll 1
    for (int db = 0; db < G1_KIT / 2; db++) {
        CP_WAIT0();            // only copy warps have outstanding groups
        __syncthreads();       // release implies group db data visible to all
        if (copier && db + 1 < G1_KIT / 2) {
            uint32_t hb = sb + ((db + 1) & 1) * (2 * G1_STAGE_B);
            size_t k0 = (size_t)(2 * db + 2) * BK;
#pragma unroll
            for (int c = 0; c < 2; c++) {
                uint32_t base = hb + c * G1_STAGE_B;
                cp_tile_w4<128>(base,                 A + k0 + c * BK, HIDDEN);
                cp_tile_w4<128>(base + TILE128_B,     G + k0 + c * BK, HIDDEN);
                cp_tile_w4<128>(base + 2 * TILE128_B, U + k0 + c * BK, HIDDEN);
            }
            CP_COMMIT();
        }
        uint32_t hb = sb + (db & 1) * (2 * G1_STAGE_B);
#pragma unroll
        for (int c = 0; c < 2; c++) {
            uint32_t st = hb + c * G1_STAGE_B;
            uint32_t sA = st, sG = st + TILE128_B, sU = st + 2 * TILE128_B;
#pragma unroll
            for (int ks = 0; ks < 4; ks++) {
                const int colb = ks * 32;
                uint32_t a[2][4], bg[8][2], bu[8][2];
#pragma unroll
                for (int m = 0; m < 2; m++)
                    load_a_frag(a[m], sA, warp_m + m * 16, colb, lane);
#pragma unroll
                for (int np = 0; np < 4; np++) {
                    load_b_frag(bg[2*np], bg[2*np+1], sG, warp_n + np * 16, colb, lane);
                    load_b_frag(bu[2*np], bu[2*np+1], sU, warp_n + np * 16, colb, lane);
                }
#pragma unroll
                for (int m = 0; m < 2; m++)
#pragma unroll
                    for (int n = 0; n < 8; n++) {
                        mma16816(ag[m][n], a[m], bg[n]);
                        mma16816(au[m][n], a[m], bu[n]);
                    }
            }
        }
    }

    // ---- Fused SwiGLU epilogue, staged through smem for coalesced stores ----
    CP_WAIT0();
    __syncthreads();
    __half* hs = reinterpret_cast<__half*>(smem);   // 128 x EP1_PITCH_H halfs
#pragma unroll
    for (int m = 0; m < 2; m++)
#pragma unroll
        for (int n = 0; n < 8; n++) {
            int row = warp_m + m * 16 + (lane >> 2);
            int col = warp_n + n * 8 + (lane & 3) * 2;
            __half2 h0 = __floats2half2_rn(silu_f(ag[m][n][0]) * au[m][n][0],
                                           silu_f(ag[m][n][1]) * au[m][n][1]);
            __half2 h1 = __floats2half2_rn(silu_f(ag[m][n][2]) * au[m][n][2],
                                           silu_f(ag[m][n][3]) * au[m][n][3]);
            *reinterpret_cast<__half2*>(hs + (size_t)row * EP1_PITCH_H + col) = h0;
            *reinterpret_cast<__half2*>(hs + (size_t)(row + 8) * EP1_PITCH_H + col) = h1;
        }
    __syncthreads();
    {
        int row = tid >> 1, seg = tid & 1;
        const uint4* src = reinterpret_cast<const uint4*>(hs + (size_t)row * EP1_PITCH_H + seg * 64);
        uint4* dst = reinterpret_cast<uint4*>(g_h + (m0 + row) * (size_t)INTER + n0 + seg * 64);
#pragma unroll
        for (int i = 0; i < 8; i++) dst[i] = src[i];
    }
}

// ============================================================================
// GEMM2: out = h @ down  (fp32 out)
// CTA 128x256, 8 warps (2m x 4n), warp 64x64. Double-chunk pipeline with the
// same copy-warp (wid>=4) prefetch role split.
// ============================================================================
__global__ void __launch_bounds__(256, 1) gemm2_kernel(float* __restrict__ out) {
    extern __shared__ char smem[];
    uint32_t sb = smem_u32(smem);

    const int tid = threadIdx.x, wid = tid >> 5, lane = tid & 31;
    const int bid = blockIdx.x;
    const int mt = bid % 16;
    const int nt = (bid / 16) % G2_NT;
    const int e  = bid / (16 * G2_NT);
    const size_t m0 = (size_t)e * T_PER_E + (size_t)mt * 128;
    const int n0 = nt * 256;

    const __half* A = g_h + m0 * INTER;
    const __half* B = g_dt + ((size_t)e * HIDDEN + n0) * INTER;

    const int warp_m = (wid & 1) * 64;
    const int warp_n = (wid >> 1) * 64;
    const bool copier = (wid >= 4);

    // Prologue: big group 0 = chunks 0,1 -> half 0 (copy warps only)
    if (copier) {
#pragma unroll
        for (int c = 0; c < 2; c++) {
            uint32_t base = sb + c * G2_STAGE_B;
            cp_tile_w4<128>(base,             A + c * BK, INTER);
            cp_tile_w4<256>(base + TILE128_B, B + c * BK, INTER);
        }
        CP_COMMIT();
    }

    float acc[4][8][4];
#pragma unroll
    for (int i = 0; i < 4; i++)
#pragma unroll
        for (int j = 0; j < 8; j++)
#pragma unroll
            for (int k = 0; k < 4; k++) acc[i][j][k] = 0.f;

#pragma unroll 1
    for (int db = 0; db < G2_KIT / 2; db++) {
        CP_WAIT0();
        __syncthreads();
        if (copier && db + 1 < G2_KIT / 2) {
            uint32_t hb = sb + ((db + 1) & 1) * (2 * G2_STAGE_B);
            size_t k0 = (size_t)(2 * db + 2) * BK;
#pragma unroll
            for (int c = 0; c < 2; c++) {
                uint32_t base = hb + c * G2_STAGE_B;
                cp_tile_w4<128>(base,             A + k0 + c * BK, INTER);
                cp_tile_w4<256>(base + TILE128_B, B + k0 + c * BK, INTER);
            }
            CP_COMMIT();
        }
        uint32_t hb = sb + (db & 1) * (2 * G2_STAGE_B);
#pragma unroll
        for (int c = 0; c < 2; c++) {
            uint32_t st = hb + c * G2_STAGE_B;
            uint32_t sA = st, sB = st + TILE128_B;
#pragma unroll
            for (int ks = 0; ks < 4; ks++) {
                const int colb = ks * 32;
                uint32_t a[4][4], b[8][2];
#pragma unroll
                for (int m = 0; m < 4; m++)
                    load_a_frag(a[m], sA, warp_m + m * 16, colb, lane);
#pragma unroll
                for (int np = 0; np < 4; np++)
                    load_b_frag(b[2*np], b[2*np+1], sB, warp_n + np * 16, colb, lane);
#pragma unroll
                for (int m = 0; m < 4; m++)
#pragma unroll
                    for (int n = 0; n < 8; n++)
                        mma16816(acc[m][n], a[m], b[n]);
            }
        }
    }

    // ---- fp32 epilogue staged through smem for coalesced 128B stores ----
    CP_WAIT0();
    __syncthreads();
    float* fs = reinterpret_cast<float*>(smem);   // 128 x EP2_PITCH_F floats
#pragma unroll
    for (int m = 0; m < 4; m++)
#pragma unroll
        for (int n = 0; n < 8; n++) {
            int row = warp_m + m * 16 + (lane >> 2);
            int col = warp_n + n * 8 + (lane & 3) * 2;
            float2 v0 = make_float2(acc[m][n][0], acc[m][n][1]);
            float2 v1 = make_float2(acc[m][n][2], acc[m][n][3]);
            *reinterpret_cast<float2*>(fs + (size_t)row * EP2_PITCH_F + col) = v0;
            *reinterpret_cast<float2*>(fs + (size_t)(row + 8) * EP2_PITCH_F + col) = v1;
        }
    __syncthreads();
    {
        int row = tid >> 1, seg = tid & 1;
        const uint4* src = reinterpret_cast<const uint4*>(fs + (size_t)row * EP2_PITCH_F + seg * 128);
        uint4* dst = reinterpret_cast<uint4*>(out + (m0 + row) * (size_t)HIDDEN + n0 + seg * 128);
#pragma unroll
        for (int i = 0; i < 32; i++) dst[i] = src[i];
    }
}

// ============================================================================
// Launch (single stream, linear graph)
// ============================================================================
extern "C" void kernel_launch(void* const* d_in, const int* in_sizes, int n_in,
                              void* d_out, int out_size) {
    const float* x  = (const float*)d_in[0];
    const float* gw = (const float*)d_in[1];
    const float* uw = (const float*)d_in[2];
    const float* dw = (const float*)d_in[3];
    float* out = (float*)d_out;

    cudaFuncSetAttribute(gemm1_kernel, cudaFuncAttributeMaxDynamicSharedMemorySize, G1_SMEM);
    cudaFuncSetAttribute(gemm2_kernel, cudaFuncAttributeMaxDynamicSharedMemorySize, G2_SMEM);

    // Fused pre-pass: cvt(x) + transpose(gw) + transpose(uw) + transpose(dw)
    prepass_kernel<<<PRE_BLKS, 256>>>(x, gw, uw, dw);

    // GEMMs
    gemm1_kernel<<<NUM_EXPERTS * G1_NT * 16, 256, G1_SMEM>>>();
    gemm2_kernel<<<NUM_EXPERTS * G2_NT * 16, 256, G2_SMEM>>>(out);
}